// round 1
// baseline (speedup 1.0000x reference)
#include <cuda_runtime.h>
#include <cuda_bf16.h>

// YOLO loss: B=32, M=50, 3 levels (80x80/s8, 40x40/s16, 20x20/s32), N=8400, C=80
// Kernel 1: 96 blocks = (b, level). Phase 1: 50 threads -> index/valid/GIoU.
//           Phase 2: 256 threads -> 50*80 focal terms. Block-reduce -> partials.
// Kernel 2: 1 block reduces 96 partials, writes scalar loss.

#define NBLK 96
#define NTHREADS 256

__device__ float g_box_part[NBLK];
__device__ float g_cls_part[NBLK];
__device__ int   g_np_part[NBLK];

__device__ __forceinline__ float softplusf(float z) {
    // log(1 + e^z), numerically stable (matches JAX log_sigmoid usage)
    return fmaxf(z, 0.0f) + log1pf(expf(-fabsf(z)));
}

__global__ void __launch_bounds__(NTHREADS) yolo_main(
    const float* __restrict__ box_preds,   // [32, 8400, 4]
    const float* __restrict__ cls_preds,   // [32, 8400, 80]
    const float* __restrict__ gt_boxes,    // [32, 50, 4]
    const int*   __restrict__ gt_labels,   // [32, 50]
    const void*  __restrict__ gt_mask)     // [32, 50] bool (byte or int32 layout)
{
    const int blk = blockIdx.x;
    const int b   = blk / 3;
    const int lvl = blk - b * 3;
    const int tid = threadIdx.x;

    int H, W, offset; float inv_s;
    if (lvl == 0)      { H = 80; W = 80; offset = 0;    inv_s = 1.0f / 8.0f;  }
    else if (lvl == 1) { H = 40; W = 40; offset = 6400; inv_s = 1.0f / 16.0f; }
    else               { H = 20; W = 20; offset = 8000; inv_s = 1.0f / 32.0f; }

    __shared__ int s_idx[50];
    __shared__ int s_lab[50];
    __shared__ int s_val[50];

    float box_acc = 0.0f;
    float cls_acc = 0.0f;
    int   np_acc  = 0;

    if (tid < 50) {
        const int m = tid;
        const float* gb = gt_boxes + ((size_t)b * 50 + m) * 4;
        const float x1 = gb[0], y1 = gb[1], x2 = gb[2], y2 = gb[3];
        const float cx = (x1 + x2) * 0.5f;
        const float cy = (y1 + y2) * 0.5f;
        const int gi = (int)floorf(cx * inv_s);
        const int gj = (int)floorf(cy * inv_s);

        // gt_mask dtype detection: all-ones byte mask -> first word 0x01010101;
        // int32 mask -> first word 0 or 1.
        bool mk;
        {
            const int first = *(const int*)gt_mask;
            if ((unsigned)first <= 1u)
                mk = ((const int*)gt_mask)[b * 50 + m] != 0;
            else
                mk = ((const unsigned char*)gt_mask)[b * 50 + m] != 0;
        }

        const bool valid = mk && (gi >= 0) && (gj >= 0) && (gi < W) && (gj < H);
        const int idx = valid ? (offset + gj * W + gi) : 0;

        s_idx[m] = idx;
        s_lab[m] = gt_labels[b * 50 + m];
        s_val[m] = valid ? 1 : 0;

        if (valid) {
            const float* pb = box_preds + ((size_t)b * 8400 + idx) * 4;
            const float px1 = pb[0], py1 = pb[1], px2 = pb[2], py2 = pb[3];

            const float ix1 = fmaxf(px1, x1), iy1 = fmaxf(py1, y1);
            const float ix2 = fminf(px2, x2), iy2 = fminf(py2, y2);
            const float inter = fmaxf(ix2 - ix1, 0.0f) * fmaxf(iy2 - iy1, 0.0f);
            const float a1 = (px2 - px1) * (py2 - py1);
            const float a2 = (x2 - x1) * (y2 - y1);
            const float uni = a1 + a2 - inter;
            const float iou = inter / uni;
            const float ex1 = fminf(px1, x1), ey1 = fminf(py1, y1);
            const float ex2 = fmaxf(px2, x2), ey2 = fmaxf(py2, y2);
            const float encl = (ex2 - ex1) * (ey2 - ey1);
            const float giou = iou - (encl - uni) / encl;
            box_acc = 1.0f - giou;
            np_acc  = 1;
        }
    }
    __syncthreads();

    // Phase 2: focal over 50*80 items
    const float* clsb = cls_preds + (size_t)b * 8400 * 80;
    for (int item = tid; item < 50 * 80; item += NTHREADS) {
        const int m = item / 80;
        const int c = item - m * 80;
        if (s_val[m]) {
            const float x = clsb[(size_t)s_idx[m] * 80 + c];
            const float p = 1.0f / (1.0f + expf(-x));
            float t;
            if (c == s_lab[m]) {
                const float q = 1.0f - p;
                t = 0.25f * q * q * softplusf(-x);   // target class
            } else {
                t = 0.75f * p * p * softplusf(x);    // non-target class
            }
            cls_acc += t;
        }
    }

    // Deterministic block reduction
    __shared__ float r0[NTHREADS];
    __shared__ float r1[NTHREADS];
    __shared__ int   r2[NTHREADS];
    r0[tid] = box_acc; r1[tid] = cls_acc; r2[tid] = np_acc;
    __syncthreads();
    #pragma unroll
    for (int s = NTHREADS / 2; s > 0; s >>= 1) {
        if (tid < s) {
            r0[tid] += r0[tid + s];
            r1[tid] += r1[tid + s];
            r2[tid] += r2[tid + s];
        }
        __syncthreads();
    }
    if (tid == 0) {
        g_box_part[blk] = r0[0];
        g_cls_part[blk] = r1[0];
        g_np_part[blk]  = r2[0];
    }
}

__global__ void __launch_bounds__(128) yolo_final(float* __restrict__ out)
{
    __shared__ float r0[128];
    __shared__ float r1[128];
    __shared__ int   r2[128];
    const int t = threadIdx.x;
    float bx = 0.0f, cl = 0.0f; int np = 0;
    if (t < NBLK) { bx = g_box_part[t]; cl = g_cls_part[t]; np = g_np_part[t]; }
    r0[t] = bx; r1[t] = cl; r2[t] = np;
    __syncthreads();
    #pragma unroll
    for (int s = 64; s > 0; s >>= 1) {
        if (t < s) {
            r0[t] += r0[t + s];
            r1[t] += r1[t + s];
            r2[t] += r2[t + s];
        }
        __syncthreads();
    }
    if (t == 0) {
        const float denom = (float)(r2[0] > 1 ? r2[0] : 1);
        out[0] = (5.0f * r0[0] + 1.0f * r1[0]) / denom;
    }
}

extern "C" void kernel_launch(void* const* d_in, const int* in_sizes, int n_in,
                              void* d_out, int out_size)
{
    const float* box_preds = (const float*)d_in[0];
    const float* cls_preds = (const float*)d_in[1];
    const float* gt_boxes  = (const float*)d_in[2];
    const int*   gt_labels = (const int*)d_in[3];
    const void*  gt_mask   = d_in[4];
    float* out = (float*)d_out;

    yolo_main<<<NBLK, NTHREADS>>>(box_preds, cls_preds, gt_boxes, gt_labels, gt_mask);
    yolo_final<<<1, 128>>>(out);
}

// round 2
// speedup vs baseline: 1.5642x; 1.5642x over previous
#include <cuda_runtime.h>
#include <cuda_bf16.h>

// YOLO loss fused single-kernel: 96 blocks = (b in 0..31, level in 0..2).
// Phase 1: 50 threads -> gather idx/valid/GIoU. Phase 2: float4 focal over 50x80.
// Block partials -> last-block-done reduction -> scalar out.

#define NBLK 96
#define NTHREADS 256

__device__ float g_box_part[NBLK];
__device__ float g_cls_part[NBLK];
__device__ int   g_np_part[NBLK];
__device__ unsigned int g_done = 0;

__device__ __forceinline__ float warp_sum(float v) {
    #pragma unroll
    for (int o = 16; o > 0; o >>= 1) v += __shfl_down_sync(0xffffffffu, v, o);
    return v;
}
__device__ __forceinline__ int warp_sum_i(int v) {
    #pragma unroll
    for (int o = 16; o > 0; o >>= 1) v += __shfl_down_sync(0xffffffffu, v, o);
    return v;
}

__global__ void __launch_bounds__(NTHREADS) yolo_fused(
    const float* __restrict__ box_preds,   // [32, 8400, 4]
    const float* __restrict__ cls_preds,   // [32, 8400, 80]
    const float* __restrict__ gt_boxes,    // [32, 50, 4]
    const int*   __restrict__ gt_labels,   // [32, 50]
    const void*  __restrict__ gt_mask,     // [32, 50] bool (byte or int32 layout)
    float*       __restrict__ out)
{
    const int blk = blockIdx.x;
    const int b   = blk / 3;
    const int lvl = blk - b * 3;
    const int tid = threadIdx.x;
    const int lane = tid & 31;
    const int wrp  = tid >> 5;

    int H, W, offset; float inv_s;
    if (lvl == 0)      { H = 80; W = 80; offset = 0;    inv_s = 1.0f / 8.0f;  }
    else if (lvl == 1) { H = 40; W = 40; offset = 6400; inv_s = 1.0f / 16.0f; }
    else               { H = 20; W = 20; offset = 8000; inv_s = 1.0f / 32.0f; }

    __shared__ int s_idx[50];
    __shared__ int s_lab[50];
    __shared__ int s_val[50];

    float box_acc = 0.0f;
    float cls_acc = 0.0f;
    int   np_acc  = 0;

    if (tid < 50) {
        const int m = tid;
        const float* gb = gt_boxes + ((size_t)b * 50 + m) * 4;
        const float x1 = gb[0], y1 = gb[1], x2 = gb[2], y2 = gb[3];
        const float cx = (x1 + x2) * 0.5f;
        const float cy = (y1 + y2) * 0.5f;
        const int gi = (int)floorf(cx * inv_s);
        const int gj = (int)floorf(cy * inv_s);

        // gt_mask dtype detection: all-ones byte mask reads as 0x01010101 in word 0.
        bool mk;
        {
            const int first = *(const int*)gt_mask;
            if ((unsigned)first <= 1u)
                mk = ((const int*)gt_mask)[b * 50 + m] != 0;
            else
                mk = ((const unsigned char*)gt_mask)[b * 50 + m] != 0;
        }

        const bool valid = mk && (gi >= 0) && (gj >= 0) && (gi < W) && (gj < H);
        const int idx = valid ? (offset + gj * W + gi) : 0;

        s_idx[m] = idx;
        s_lab[m] = gt_labels[b * 50 + m];
        s_val[m] = valid ? 1 : 0;

        if (valid) {
            const float4 pbv = *(const float4*)(box_preds + ((size_t)b * 8400 + idx) * 4);
            const float px1 = pbv.x, py1 = pbv.y, px2 = pbv.z, py2 = pbv.w;

            const float ix1 = fmaxf(px1, x1), iy1 = fmaxf(py1, y1);
            const float ix2 = fminf(px2, x2), iy2 = fminf(py2, y2);
            const float inter = fmaxf(ix2 - ix1, 0.0f) * fmaxf(iy2 - iy1, 0.0f);
            const float a1 = (px2 - px1) * (py2 - py1);
            const float a2 = (x2 - x1) * (y2 - y1);
            const float uni = a1 + a2 - inter;
            const float iou = inter / uni;
            const float ex1 = fminf(px1, x1), ey1 = fminf(py1, y1);
            const float ex2 = fmaxf(px2, x2), ey2 = fmaxf(py2, y2);
            const float encl = (ex2 - ex1) * (ey2 - ey1);
            const float giou = iou - (encl - uni) / encl;
            box_acc = 1.0f - giou;
            np_acc  = 1;
        }
    }
    __syncthreads();

    // Phase 2: focal over 50 rows x 20 float4 chunks = 1000 items
    const float* clsb = cls_preds + (size_t)b * 8400 * 80;
    #pragma unroll
    for (int it = 0; it < 4; it++) {
        const int item = tid + it * NTHREADS;   // < 1024; guard at 1000
        if (item < 1000) {
            const int m  = item / 20;
            const int c4 = (item - m * 20) * 4;
            if (s_val[m]) {
                const float4 xv = *(const float4*)(clsb + (size_t)s_idx[m] * 80 + c4);
                const int lab = s_lab[m];
                const float xs[4] = {xv.x, xv.y, xv.z, xv.w};
                #pragma unroll
                for (int k = 0; k < 4; k++) {
                    const float x = xs[k];
                    const float e = __expf(-x);
                    const float inv = 1.0f / (1.0f + e);
                    const float L = __logf(1.0f + e);     // softplus(-x)
                    if (c4 + k == lab) {
                        const float q = e * inv;          // 1 - sigmoid(x)
                        cls_acc += 0.25f * q * q * L;
                    } else {
                        const float p = inv;              // sigmoid(x)
                        cls_acc += 0.75f * p * p * (x + L);  // softplus(x)
                    }
                }
            }
        }
    }

    // Block reduction: warp shuffle -> smem[8] -> warp 0
    __shared__ float w0[8], w1[8];
    __shared__ int   w2[8];
    float rb = warp_sum(box_acc);
    float rc = warp_sum(cls_acc);
    int   rn = warp_sum_i(np_acc);
    if (lane == 0) { w0[wrp] = rb; w1[wrp] = rc; w2[wrp] = rn; }
    __syncthreads();
    if (wrp == 0) {
        float vb = (lane < 8) ? w0[lane] : 0.0f;
        float vc = (lane < 8) ? w1[lane] : 0.0f;
        int   vn = (lane < 8) ? w2[lane] : 0;
        vb = warp_sum(vb); vc = warp_sum(vc); vn = warp_sum_i(vn);
        if (lane == 0) {
            g_box_part[blk] = vb;
            g_cls_part[blk] = vc;
            g_np_part[blk]  = vn;
        }
    }

    // Last-block-done final reduction
    __shared__ bool s_last;
    __threadfence();
    if (tid == 0) {
        unsigned old = atomicAdd(&g_done, 1u);
        s_last = (old == NBLK - 1);
    }
    __syncthreads();
    if (s_last) {
        float vb = 0.0f, vc = 0.0f; int vn = 0;
        if (tid < NBLK) {
            vb = *((volatile float*)&g_box_part[tid]);
            vc = *((volatile float*)&g_cls_part[tid]);
            vn = *((volatile int*)&g_np_part[tid]);
        }
        vb = warp_sum(vb); vc = warp_sum(vc); vn = warp_sum_i(vn);
        __shared__ float f0[3], f1[3];
        __shared__ int   f2[3];
        if (lane == 0 && wrp < 3) { f0[wrp] = vb; f1[wrp] = vc; f2[wrp] = vn; }
        __syncthreads();
        if (tid == 0) {
            const float sb = f0[0] + f0[1] + f0[2];
            const float sc = f1[0] + f1[1] + f1[2];
            const int   sn = f2[0] + f2[1] + f2[2];
            const float denom = (float)(sn > 1 ? sn : 1);
            out[0] = (5.0f * sb + sc) / denom;
            g_done = 0;   // reset for next graph replay
        }
    }
}

extern "C" void kernel_launch(void* const* d_in, const int* in_sizes, int n_in,
                              void* d_out, int out_size)
{
    const float* box_preds = (const float*)d_in[0];
    const float* cls_preds = (const float*)d_in[1];
    const float* gt_boxes  = (const float*)d_in[2];
    const int*   gt_labels = (const int*)d_in[3];
    const void*  gt_mask   = d_in[4];
    float* out = (float*)d_out;

    yolo_fused<<<NBLK, NTHREADS>>>(box_preds, cls_preds, gt_boxes, gt_labels, gt_mask, out);
}

// round 4
// speedup vs baseline: 1.9336x; 1.2362x over previous
#include <cuda_runtime.h>
#include <cuda_bf16.h>

// YOLO loss, fully flattened: 1 thread = 1 float4 cls chunk.
// 32 b x 3 lvl x 50 m x 20 chunks = 96000 threads = 375 blocks x 256.
// chunk==0 threads also compute the GIoU/box term for their (b,lvl,m).
// Deterministic block partials + last-block-done final reduction.

#define NPART 375
#define NTHREADS 256

__device__ float g_box_part[NPART];
__device__ float g_cls_part[NPART];
__device__ int   g_np_part[NPART];
__device__ unsigned int g_done = 0;

__device__ __forceinline__ float warp_sum(float v) {
    #pragma unroll
    for (int o = 16; o > 0; o >>= 1) v += __shfl_down_sync(0xffffffffu, v, o);
    return v;
}
__device__ __forceinline__ int warp_sum_i(int v) {
    #pragma unroll
    for (int o = 16; o > 0; o >>= 1) v += __shfl_down_sync(0xffffffffu, v, o);
    return v;
}

__global__ void __launch_bounds__(NTHREADS) yolo_flat(
    const float* __restrict__ box_preds,   // [32, 8400, 4]
    const float* __restrict__ cls_preds,   // [32, 8400, 80]
    const float* __restrict__ gt_boxes,    // [32, 50, 4]
    const int*   __restrict__ gt_labels,   // [32, 50]
    const void*  __restrict__ gt_mask,     // [32, 50] bool (byte or int32 layout)
    float*       __restrict__ out)
{
    const int tid  = threadIdx.x;
    const int item = blockIdx.x * NTHREADS + tid;   // < 96000 always (375*256)
    const int lane = tid & 31;
    const int wrp  = tid >> 5;

    // decode: item = ((b*3 + lvl)*50 + m)*20 + chunk
    const int chunk = item % 20;
    int t = item / 20;
    const int m = t % 50;
    t /= 50;
    const int lvl = t % 3;
    const int b = t / 3;

    int HW, W, offset; float inv_s;
    if (lvl == 0)      { HW = 80; W = 80; offset = 0;    inv_s = 1.0f / 8.0f;  }
    else if (lvl == 1) { HW = 40; W = 40; offset = 6400; inv_s = 1.0f / 16.0f; }
    else               { HW = 20; W = 20; offset = 8000; inv_s = 1.0f / 32.0f; }

    // Independent loads issued up-front (overlap latencies)
    const float4 gb = __ldg((const float4*)(gt_boxes + ((size_t)b * 50 + m) * 4));
    const int lab = __ldg(gt_labels + b * 50 + m);
    bool mk;
    {
        const int first = *(const int*)gt_mask;   // dtype probe (broadcast, cached)
        if ((unsigned)first <= 1u)
            mk = ((const int*)gt_mask)[b * 50 + m] != 0;
        else
            mk = ((const unsigned char*)gt_mask)[b * 50 + m] != 0;
    }

    const float x1 = gb.x, y1 = gb.y, x2 = gb.z, y2 = gb.w;
    const float cx = (x1 + x2) * 0.5f;
    const float cy = (y1 + y2) * 0.5f;
    const int gi = (int)floorf(cx * inv_s);
    const int gj = (int)floorf(cy * inv_s);
    const bool valid = mk && (gi >= 0) && (gj >= 0) && (gi < W) && (gj < HW);
    const int idx = valid ? (offset + gj * W + gi) : 0;

    float cls_acc = 0.0f;
    float box_acc = 0.0f;
    int   np_acc  = 0;

    if (valid) {
        const float4 xv = __ldg((const float4*)(cls_preds +
                                ((size_t)b * 8400 + idx) * 80 + chunk * 4));
        const int c4 = chunk * 4;
        const float xs[4] = {xv.x, xv.y, xv.z, xv.w};
        #pragma unroll
        for (int k = 0; k < 4; k++) {
            const float x = xs[k];
            const float e = __expf(-x);
            const float inv = 1.0f / (1.0f + e);
            const float L = __logf(1.0f + e);        // softplus(-x)
            if (c4 + k == lab) {
                const float q = e * inv;             // 1 - sigmoid(x)
                cls_acc += 0.25f * q * q * L;
            } else {
                const float p = inv;                 // sigmoid(x)
                cls_acc += 0.75f * p * p * (x + L);  // softplus(x)
            }
        }

        if (chunk == 0) {
            const float4 pbv = __ldg((const float4*)(box_preds +
                                     ((size_t)b * 8400 + idx) * 4));
            const float px1 = pbv.x, py1 = pbv.y, px2 = pbv.z, py2 = pbv.w;
            const float ix1 = fmaxf(px1, x1), iy1 = fmaxf(py1, y1);
            const float ix2 = fminf(px2, x2), iy2 = fminf(py2, y2);
            const float inter = fmaxf(ix2 - ix1, 0.0f) * fmaxf(iy2 - iy1, 0.0f);
            const float a1 = (px2 - px1) * (py2 - py1);
            const float a2 = (x2 - x1) * (y2 - y1);
            const float uni = a1 + a2 - inter;
            const float iou = inter / uni;
            const float ex1 = fminf(px1, x1), ey1 = fminf(py1, y1);
            const float ex2 = fmaxf(px2, x2), ey2 = fmaxf(py2, y2);
            const float encl = (ex2 - ex1) * (ey2 - ey1);
            const float giou = iou - (encl - uni) / encl;
            box_acc = 1.0f - giou;
            np_acc  = 1;
        }
    }

    // Block reduction: warp shuffle -> smem -> warp 0
    __shared__ float w0[8], w1[8];
    __shared__ int   w2[8];
    float rb = warp_sum(box_acc);
    float rc = warp_sum(cls_acc);
    int   rn = warp_sum_i(np_acc);
    if (lane == 0) { w0[wrp] = rb; w1[wrp] = rc; w2[wrp] = rn; }
    __syncthreads();
    if (wrp == 0) {
        float vb = (lane < 8) ? w0[lane] : 0.0f;
        float vc = (lane < 8) ? w1[lane] : 0.0f;
        int   vn = (lane < 8) ? w2[lane] : 0;
        vb = warp_sum(vb); vc = warp_sum(vc); vn = warp_sum_i(vn);
        if (lane == 0) {
            g_box_part[blockIdx.x] = vb;
            g_cls_part[blockIdx.x] = vc;
            g_np_part[blockIdx.x]  = vn;
        }
    }

    // Last-block-done final reduction (375 partials)
    __shared__ bool s_last;
    __threadfence();
    if (tid == 0) {
        unsigned old = atomicAdd(&g_done, 1u);
        s_last = (old == NPART - 1);
    }
    __syncthreads();
    if (s_last) {
        float vb = 0.0f, vc = 0.0f; int vn = 0;
        if (tid < NPART) {
            vb = *((volatile float*)&g_box_part[tid]);
            vc = *((volatile float*)&g_cls_part[tid]);
            vn = *((volatile int*)&g_np_part[tid]);
        }
        const int tid2 = tid + NTHREADS;
        if (tid2 < NPART) {
            vb += *((volatile float*)&g_box_part[tid2]);
            vc += *((volatile float*)&g_cls_part[tid2]);
            vn += *((volatile int*)&g_np_part[tid2]);
        }
        vb = warp_sum(vb); vc = warp_sum(vc); vn = warp_sum_i(vn);
        __shared__ float f0[8], f1[8];
        __shared__ int   f2[8];
        if (lane == 0) { f0[wrp] = vb; f1[wrp] = vc; f2[wrp] = vn; }
        __syncthreads();
        if (tid == 0) {
            float sb = 0.0f, sc = 0.0f; int sn = 0;
            #pragma unroll
            for (int i = 0; i < 8; i++) { sb += f0[i]; sc += f1[i]; sn += f2[i]; }
            const float denom = (float)(sn > 1 ? sn : 1);
            out[0] = (5.0f * sb + sc) / denom;
            g_done = 0;   // reset for next graph replay
        }
    }
}

extern "C" void kernel_launch(void* const* d_in, const int* in_sizes, int n_in,
                              void* d_out, int out_size)
{
    const float* box_preds = (const float*)d_in[0];
    const float* cls_preds = (const float*)d_in[1];
    const float* gt_boxes  = (const float*)d_in[2];
    const int*   gt_labels = (const int*)d_in[3];
    const void*  gt_mask   = d_in[4];
    float* out = (float*)d_out;

    yolo_flat<<<NPART, NTHREADS>>>(box_preds, cls_preds, gt_boxes, gt_labels, gt_mask, out);
}